// round 12
// baseline (speedup 1.0000x reference)
#include <cuda_runtime.h>
#include <cuda_fp16.h>
#include <cstdint>

#define N_NODES   131072
#define N_EDGES   2097152
#define RANK      256
#define L_FLOW    128
#define BATCH     1024
#define N_CLASSES 32
#define ORDER     3
#define BN_EPS    1e-5f

// ---------------------------------------------------------------------------
// Scratch
// ---------------------------------------------------------------------------
__device__ __half2 g_Yi[(size_t)N_NODES * RANK];   // interleaved (h,l)
__device__ __half  g_Ah[(size_t)N_NODES * RANK];
__device__ __half  g_Al[(size_t)N_NODES * RANK];
__device__ __half  g_Bh[(size_t)N_NODES * RANK];
__device__ __half  g_Bl[(size_t)N_NODES * RANK];
__device__ __half  g_Wph[RANK * RANK];
__device__ __half  g_Wpm[RANK * RANK];
__device__ float   g_ro[BATCH * RANK * ORDER];
__device__ float   g_stats9[9 * 2 * RANK];   // per-sublayer col sum/sumsq
__device__ float   g_cvec9[9 * RANK];        // per-sublayer bb^T W
__device__ float   g_degw[N_NODES];
__device__ int     g_cnt[N_NODES];
__device__ int     g_off[N_NODES];
__device__ int     g_cur[N_NODES];
__device__ int     g_csr[N_EDGES];
__device__ int     g_bsum[256];

__device__ __forceinline__ uint32_t smem_u32(const void* p) {
    uint32_t a;
    asm("{ .reg .u64 t; cvta.to.shared.u64 t, %1; cvt.u32.u64 %0, t; }"
        : "=r"(a) : "l"(p));
    return a;
}
__device__ __forceinline__ void ldsm_x4(uint32_t* r, uint32_t addr) {
    asm volatile("ldmatrix.sync.aligned.m8n8.x4.shared.b16 {%0,%1,%2,%3}, [%4];"
                 : "=r"(r[0]), "=r"(r[1]), "=r"(r[2]), "=r"(r[3]) : "r"(addr));
}
__device__ __forceinline__ void mma_f16(float* c, const uint32_t* a,
                                        uint32_t b0, uint32_t b1) {
    asm volatile(
        "mma.sync.aligned.m16n8k16.row.col.f32.f16.f16.f32 "
        "{%0,%1,%2,%3}, {%4,%5,%6,%7}, {%8,%9}, {%0,%1,%2,%3};"
        : "+f"(c[0]), "+f"(c[1]), "+f"(c[2]), "+f"(c[3])
        : "r"(a[0]), "r"(a[1]), "r"(a[2]), "r"(a[3]), "r"(b0), "r"(b1));
}
__device__ __forceinline__ void cp16(uint32_t s, const void* g) {
    asm volatile("cp.async.cg.shared.global [%0], [%1], 16;"
                 :: "r"(s), "l"(g) : "memory");
}
#define CP_COMMIT() asm volatile("cp.async.commit_group;" ::: "memory")
#define CP_WAIT0()  asm volatile("cp.async.wait_group 0;" ::: "memory")

__device__ __forceinline__ uint32_t pack_h2(float a, float b) {
    __half2 p = __halves2half2(__float2half_rn(a), __float2half_rn(b));
    return *(uint32_t*)&p;
}
__device__ __forceinline__ void st_cs_u32(void* p, uint32_t a) {
    asm volatile("st.global.cs.u32 [%0], %1;" :: "l"(p), "r"(a) : "memory");
}

// ---------------------------------------------------------------------------
// 1) seq encoder -> interleaved Yi
// ---------------------------------------------------------------------------
__global__ void encode_kernel(const float* __restrict__ nv,
                              const float* __restrict__ sW,
                              const float* __restrict__ sb,
                              __half2* __restrict__ Yi) {
    const size_t total = (size_t)N_NODES * 32;
    for (size_t idx = (size_t)blockIdx.x * blockDim.x + threadIdx.x;
         idx < total; idx += (size_t)gridDim.x * blockDim.x) {
        size_t n = idx >> 5;
        int    q = (int)(idx & 31);
        float  x = __ldg(nv + n);
        float v[8];
        #pragma unroll
        for (int j = 0; j < 2; j++) {
            float4 w = __ldg((const float4*)sW + q * 2 + j);
            float4 b = __ldg((const float4*)sb + q * 2 + j);
            v[j * 4 + 0] = fmaf(x, w.x, b.x);
            v[j * 4 + 1] = fmaf(x, w.y, b.y);
            v[j * 4 + 2] = fmaf(x, w.z, b.z);
            v[j * 4 + 3] = fmaf(x, w.w, b.w);
        }
        uint4 o0, o1;
        uint32_t* p0 = (uint32_t*)&o0;
        uint32_t* p1 = (uint32_t*)&o1;
        #pragma unroll
        for (int j = 0; j < 4; j++) {
            float h0 = __half2float(__float2half_rn(v[j]));
            float h1 = __half2float(__float2half_rn(v[4 + j]));
            p0[j] = pack_h2(h0, v[j] - h0);
            p1[j] = pack_h2(h1, v[4 + j] - h1);
        }
        uint4* dst = (uint4*)(Yi + n * RANK + q * 8);
        dst[0] = o0;
        dst[1] = o1;
    }
}

// ---------------------------------------------------------------------------
// 2) CSR build + upfront zero
// ---------------------------------------------------------------------------
__global__ void zero_cnt_kernel(int* __restrict__ cnt) {
    cnt[blockIdx.x * blockDim.x + threadIdx.x] = 0;
}
__global__ void zero_misc_kernel(float* __restrict__ stats9,
                                 float* __restrict__ cvec9,
                                 float* __restrict__ ro) {
    const int i = blockIdx.x * blockDim.x + threadIdx.x;
    if (i < 9 * 2 * RANK) stats9[i] = 0.f;
    if (i < 9 * RANK)     cvec9[i]  = 0.f;
    if (i < BATCH * RANK * ORDER) ro[i] = 0.f;
}
__global__ void hist_kernel(const int* __restrict__ ed, int* __restrict__ cnt) {
    atomicAdd(&cnt[ed[blockIdx.x * blockDim.x + threadIdx.x]], 1);
}
__global__ void scan1_kernel(const int* __restrict__ cnt, int* __restrict__ bsum) {
    __shared__ int s[512];
    const int t = threadIdx.x;
    s[t] = cnt[blockIdx.x * 512 + t];
    __syncthreads();
    for (int o = 256; o > 0; o >>= 1) {
        if (t < o) s[t] += s[t + o];
        __syncthreads();
    }
    if (t == 0) bsum[blockIdx.x] = s[0];
}
__global__ void scan2_kernel(int* __restrict__ bsum) {
    __shared__ int s[256];
    const int t = threadIdx.x;
    int v = bsum[t];
    s[t] = v;
    __syncthreads();
    for (int o = 1; o < 256; o <<= 1) {
        int add = (t >= o) ? s[t - o] : 0;
        __syncthreads();
        s[t] += add;
        __syncthreads();
    }
    bsum[t] = s[t] - v;
}
__global__ void scan3_kernel(const int* __restrict__ cnt, const int* __restrict__ bsum,
                             int* __restrict__ off, int* __restrict__ cur,
                             float* __restrict__ degw) {
    __shared__ int s[512];
    const int t = threadIdx.x;
    const int base = blockIdx.x * 512;
    int v = cnt[base + t];
    s[t] = v;
    __syncthreads();
    for (int o = 1; o < 512; o <<= 1) {
        int add = (t >= o) ? s[t - o] : 0;
        __syncthreads();
        s[t] += add;
        __syncthreads();
    }
    int ex = s[t] - v + bsum[blockIdx.x];
    off[base + t]  = ex;
    cur[base + t]  = ex;
    degw[base + t] = 1.0f + (float)v;
}
__global__ void fill_kernel(const int* __restrict__ es, const int* __restrict__ ed,
                            int* __restrict__ cur, int* __restrict__ csr) {
    const int e = blockIdx.x * blockDim.x + threadIdx.x;
    int p = atomicAdd(&cur[ed[e]], 1);
    csr[p] = es[e];
}

// ---------------------------------------------------------------------------
// 3) gather (feature-QUARTER pass, 32MB working set, L2-resident).
//    lane covers 2 features (uint2 = 8B); warp = 256B contiguous.
// ---------------------------------------------------------------------------
__global__ void gather_kernel(const __half2* __restrict__ Yi,
                              __half* __restrict__ Zh, __half* __restrict__ Zl,
                              const int* __restrict__ off,
                              const int* __restrict__ cnt,
                              const int* __restrict__ csr, int qf) {
    const int node = blockIdx.x * 8 + (threadIdx.x >> 5);
    const int lane = threadIdx.x & 31;
    const int foff = qf * 64;
    float acc0, acc1;
    {
        uint2 v = __ldg((const uint2*)(Yi + (size_t)node * RANK + foff) + lane);
        float2 f0 = __half22float2(*(__half2*)&v.x);
        float2 f1 = __half22float2(*(__half2*)&v.y);
        acc0 = f0.x + f0.y;
        acc1 = f1.x + f1.y;
    }
    const int o = off[node];
    const int d = cnt[node];
    int j = 0;
    for (; j + 2 <= d; j += 2) {
        const size_t s0 = (size_t)__ldg(csr + o + j)     * RANK + foff;
        const size_t s1 = (size_t)__ldg(csr + o + j + 1) * RANK + foff;
        uint2 v0 = __ldg((const uint2*)(Yi + s0) + lane);
        uint2 v1 = __ldg((const uint2*)(Yi + s1) + lane);
        float2 a0 = __half22float2(*(__half2*)&v0.x);
        float2 a1 = __half22float2(*(__half2*)&v0.y);
        float2 b0 = __half22float2(*(__half2*)&v1.x);
        float2 b1 = __half22float2(*(__half2*)&v1.y);
        acc0 += (a0.x + a0.y) + (b0.x + b0.y);
        acc1 += (a1.x + a1.y) + (b1.x + b1.y);
    }
    if (j < d) {
        const size_t s = (size_t)__ldg(csr + o + j) * RANK + foff;
        uint2 v = __ldg((const uint2*)(Yi + s) + lane);
        float2 f0 = __half22float2(*(__half2*)&v.x);
        float2 f1 = __half22float2(*(__half2*)&v.y);
        acc0 += f0.x + f0.y;
        acc1 += f1.x + f1.y;
    }
    float h0 = __half2float(__float2half_rn(acc0));
    float h1 = __half2float(__float2half_rn(acc1));
    const size_t zo = (size_t)node * RANK + foff + lane * 2;
    st_cs_u32(Zh + zo, pack_h2(h0, h1));
    st_cs_u32(Zl + zo, pack_h2(acc0 - h0, acc1 - h1));
}

// ---------------------------------------------------------------------------
// 4) weight fold with inline pending-BN affine:
//    a,bb computed from stats_prev (null => identity); W' = diag(a) W;
//    cvec[s] += bb^T W.
// ---------------------------------------------------------------------------
__global__ void prep_wfold_kernel(const float* __restrict__ W,
                                  const float* __restrict__ stats_prev,
                                  const float* __restrict__ gamma_prev,
                                  const float* __restrict__ beta_prev,
                                  __half* __restrict__ Wph,
                                  __half* __restrict__ Wpm,
                                  float* __restrict__ cvec) {
    __shared__ float t[32][33];
    __shared__ float cp[32][33];
    __shared__ float a_s[32], bb_s[32];
    const int tx = threadIdx.x, ty = threadIdx.y;
    if (ty == 0) {
        const int k = blockIdx.y * 32 + tx;
        float a = 1.f, bb = 0.f;
        if (stats_prev) {
            const float inv = 1.0f / (float)N_NODES;
            float m   = stats_prev[k] * inv;
            float var = fmaf(-m, m, stats_prev[RANK + k] * inv);
            a  = gamma_prev[k] * rsqrtf(var + BN_EPS);
            bb = fmaf(-m, a, beta_prev[k]);
        }
        a_s[tx]  = a;
        bb_s[tx] = bb;
    }
    const int k   = blockIdx.y * 32 + ty;
    const int out = blockIdx.x * 32 + tx;
    float w = W[(size_t)k * RANK + out];
    t[ty][tx] = w;
    __syncthreads();
    cp[ty][tx] = bb_s[ty] * w;
    __syncthreads();
    for (int o = 16; o > 0; o >>= 1) {
        if (ty < o) cp[ty][tx] += cp[ty + o][tx];
        __syncthreads();
    }
    if (ty == 0) atomicAdd(&cvec[out], cp[0][tx]);
    const int kp   = blockIdx.y * 32 + tx;
    const int outp = blockIdx.x * 32 + ty;
    float wv = a_s[tx] * t[tx][ty];
    __half h = __float2half_rn(wv);
    __half m = __float2half_rn(wv - __half2float(h));
    Wph[(size_t)outp * RANK + kp] = h;
    Wpm[(size_t)outp * RANK + kp] = m;
}

// ---------------------------------------------------------------------------
// 5) GEMM: 128x128 tile, 256 thr, 2-stage cp.async, one sync per k-chunk.
// ---------------------------------------------------------------------------
#define TS        80
#define TILE      (128 * TS)
#define STAGE     (4 * TILE)
#define GEMM_SMEM (2 * STAGE)

__global__ void __launch_bounds__(256, 2)
gemm_tc_kernel(const __half* __restrict__ Xh, const __half* __restrict__ Xl,
               const __half* __restrict__ Wph, const __half* __restrict__ Wpm,
               const float* __restrict__ bias, const float* __restrict__ cvec,
               const float* __restrict__ degw,
               __half* __restrict__ Yh, __half* __restrict__ Yl,
               __half2* __restrict__ Yi,
               float* __restrict__ stats, float* __restrict__ rosum) {
    extern __shared__ char smem[];
    const uint32_t sbase = smem_u32(smem);
    const int tid  = threadIdx.x;
    const int wid  = tid >> 5;
    const int lane = tid & 31;
    const int wm_  = wid & 3;
    const int wn   = wid >> 2;
    const int outbase = blockIdx.x * 128;
    const int x0      = blockIdx.y * 128;

    const int lr  = tid >> 1;
    const int lsb = (tid & 1) * 32;
    const int lsh = (tid & 1) * 16;
    const char* gsrc[4];
    gsrc[0] = (const char*)(Xh  + (size_t)(x0 + lr)      * RANK + lsh);
    gsrc[1] = (const char*)(Xl  + (size_t)(x0 + lr)      * RANK + lsh);
    gsrc[2] = (const char*)(Wph + (size_t)(outbase + lr) * RANK + lsh);
    gsrc[3] = (const char*)(Wpm + (size_t)(outbase + lr) * RANK + lsh);
    uint32_t sdst[4];
    #pragma unroll
    for (int t = 0; t < 4; t++) sdst[t] = sbase + t * TILE + lr * TS + lsb;

    float acc[2][8][4];
    #pragma unroll
    for (int mi = 0; mi < 2; mi++)
        #pragma unroll
        for (int nt = 0; nt < 8; nt++)
            #pragma unroll
            for (int e = 0; e < 4; e++) acc[mi][nt][e] = 0.f;

    const uint32_t aA = sbase + (uint32_t)(wm_ * 32 + (lane & 15)) * TS
                        + ((uint32_t)(lane >> 4) << 4);
    const uint32_t aB = sbase + 2 * TILE
                        + (uint32_t)(wn * 64 + ((lane >> 4) << 3) + (lane & 7)) * TS
                        + (((uint32_t)(lane >> 3) & 1) << 4);

    #pragma unroll
    for (int t = 0; t < 4; t++) {
        cp16(sdst[t],      gsrc[t]);
        cp16(sdst[t] + 16, gsrc[t] + 16);
    }
    CP_COMMIT();

    #pragma unroll 1
    for (int c = 0; c < 8; c++) {
        CP_WAIT0();
        __syncthreads();

        if (c < 7) {
            const int st = ((c + 1) & 1) * STAGE;
            const int go = (c + 1) * 64;
            #pragma unroll
            for (int t = 0; t < 4; t++) {
                cp16(sdst[t] + st,      gsrc[t] + go);
                cp16(sdst[t] + st + 16, gsrc[t] + go + 16);
            }
            CP_COMMIT();
        }

        const uint32_t st = (uint32_t)((c & 1) * STAGE);
        #pragma unroll
        for (int t = 0; t < 2; t++) {
            uint32_t ah[2][4], am[2][4];
            const uint32_t aAt = aA + st + t * 32;
            ldsm_x4(ah[0], aAt);
            ldsm_x4(ah[1], aAt + 16 * TS);
            ldsm_x4(am[0], aAt + TILE);
            ldsm_x4(am[1], aAt + TILE + 16 * TS);
            const uint32_t aBt = aB + st + t * 32;
            #pragma unroll
            for (int g = 0; g < 4; g++) {
                uint32_t bh[4], bm[4];
                ldsm_x4(bh, aBt + g * 16 * TS);
                ldsm_x4(bm, aBt + g * 16 * TS + TILE);
                #pragma unroll
                for (int mi = 0; mi < 2; mi++) {
                    #pragma unroll
                    for (int s = 0; s < 2; s++) {
                        float* cc = acc[mi][g * 2 + s];
                        mma_f16(cc, ah[mi], bh[2 * s], bh[2 * s + 1]);
                        mma_f16(cc, ah[mi], bm[2 * s], bm[2 * s + 1]);
                        mma_f16(cc, am[mi], bh[2 * s], bh[2 * s + 1]);
                    }
                }
            }
        }
    }

    // --- epilogue ---
    const int gid = lane >> 2, tig = lane & 3;
    float df[4] = {1.f, 1.f, 1.f, 1.f};
    if (degw) {
        const int rb = x0 + wm_ * 32 + gid;
        df[0] = degw[rb];
        df[1] = degw[rb + 8];
        df[2] = degw[rb + 16];
        df[3] = degw[rb + 24];
    }
    float ssum[8][2], ssq[8][2];
    #pragma unroll
    for (int nt = 0; nt < 8; nt++) {
        const int out = outbase + wn * 64 + nt * 8 + 2 * tig;
        const float b0 = __ldg(bias + out),  b1 = __ldg(bias + out + 1);
        const float c0 = __ldg(cvec + out),  c1 = __ldg(cvec + out + 1);
        float s0 = 0.f, s1 = 0.f, q0 = 0.f, q1 = 0.f;
        #pragma unroll
        for (int mi = 0; mi < 2; mi++) {
            const float* cc = acc[mi][nt];
            const int row = x0 + wm_ * 32 + mi * 16 + gid;
            float v00 = fmaxf(cc[0] + b0 + df[2 * mi] * c0, 0.f);
            float v01 = fmaxf(cc[1] + b1 + df[2 * mi] * c1, 0.f);
            float v10 = fmaxf(cc[2] + b0 + df[2 * mi + 1] * c0, 0.f);
            float v11 = fmaxf(cc[3] + b1 + df[2 * mi + 1] * c1, 0.f);
            float h00 = __half2float(__float2half_rn(v00));
            float h01 = __half2float(__float2half_rn(v01));
            float h10 = __half2float(__float2half_rn(v10));
            float h11 = __half2float(__float2half_rn(v11));
            if (Yi) {
                *(uint2*)(Yi + (size_t)row * RANK + out) =
                    make_uint2(pack_h2(h00, v00 - h00), pack_h2(h01, v01 - h01));
                *(uint2*)(Yi + (size_t)(row + 8) * RANK + out) =
                    make_uint2(pack_h2(h10, v10 - h10), pack_h2(h11, v11 - h11));
            } else {
                *(uint32_t*)(Yh + (size_t)row * RANK + out)       = pack_h2(h00, h01);
                *(uint32_t*)(Yl + (size_t)row * RANK + out)       = pack_h2(v00 - h00, v01 - h01);
                *(uint32_t*)(Yh + (size_t)(row + 8) * RANK + out) = pack_h2(h10, h11);
                *(uint32_t*)(Yl + (size_t)(row + 8) * RANK + out) = pack_h2(v10 - h10, v11 - h11);
            }
            s0 += v00 + v10;
            s1 += v01 + v11;
            q0 += v00 * v00 + v10 * v10;
            q1 += v01 * v01 + v11 * v11;
        }
        ssum[nt][0] = s0; ssum[nt][1] = s1;
        ssq[nt][0]  = q0; ssq[nt][1]  = q1;
    }
    #pragma unroll
    for (int nt = 0; nt < 8; nt++)
        #pragma unroll
        for (int e = 0; e < 2; e++) {
            float s = ssum[nt][e], q = ssq[nt][e];
            #pragma unroll
            for (int m = 4; m < 32; m <<= 1) {
                s += __shfl_xor_sync(0xFFFFFFFF, s, m);
                q += __shfl_xor_sync(0xFFFFFFFF, q, m);
            }
            ssum[nt][e] = s; ssq[nt][e] = q;
        }
    if (lane < 4) {
        float* rp = rosum ? rosum + (size_t)blockIdx.y * (RANK * ORDER) : nullptr;
        #pragma unroll
        for (int nt = 0; nt < 8; nt++) {
            const int out = outbase + wn * 64 + nt * 8 + 2 * tig;
            atomicAdd(&stats[out],            ssum[nt][0]);
            atomicAdd(&stats[out + 1],        ssum[nt][1]);
            atomicAdd(&stats[RANK + out],     ssq[nt][0]);
            atomicAdd(&stats[RANK + out + 1], ssq[nt][1]);
            if (rp) {
                atomicAdd(rp + out,     ssum[nt][0]);
                atomicAdd(rp + out + 1, ssum[nt][1]);
            }
        }
    }
}

// ---------------------------------------------------------------------------
// 6) readout scale: computes pending affine inline from final sublayer stats
// ---------------------------------------------------------------------------
__global__ void scale_ro_kernel(float* __restrict__ ro,
                                const float* __restrict__ stats,
                                const float* __restrict__ gamma,
                                const float* __restrict__ beta) {
    const int c = threadIdx.x;
    const float inv = 1.0f / (float)N_NODES;
    float m   = stats[c] * inv;
    float var = fmaf(-m, m, stats[RANK + c] * inv);
    float a   = gamma[c] * rsqrtf(var + BN_EPS);
    float bb  = fmaf(-m, a, beta[c]);
    float* p = ro + (size_t)blockIdx.x * (RANK * ORDER) + c;
    *p = fmaf(a, *p, 128.f * bb);
}

// ---------------------------------------------------------------------------
// 7) classifier
// ---------------------------------------------------------------------------
__global__ void classifier_kernel(const float* __restrict__ ro,
                                  const float* __restrict__ W,
                                  const float* __restrict__ b,
                                  float* __restrict__ out) {
    const int bi = blockIdx.x;
    const int c  = threadIdx.x;
    const float* r = ro + (size_t)bi * (RANK * ORDER);
    float acc = b[c];
    #pragma unroll 8
    for (int k = 0; k < RANK * ORDER; k++)
        acc = fmaf(r[k], W[(size_t)k * N_CLASSES + c], acc);
    out[(size_t)bi * N_CLASSES + c] = acc;
}

// ---------------------------------------------------------------------------
// Host driver
// ---------------------------------------------------------------------------
extern "C" void kernel_launch(void* const* d_in, const int* in_sizes, int n_in,
                              void* d_out, int out_size) {
    const float* node_vals = (const float*)d_in[0];
    const int*   edge_src  = (const int*)d_in[1];
    const int*   edge_dst  = (const int*)d_in[2];
    const float* seq_W     = (const float*)d_in[3];
    const float* seq_b     = (const float*)d_in[4];
    const float* mlp_W     = (const float*)d_in[5];
    const float* mlp_b     = (const float*)d_in[6];
    const float* bn_gamma  = (const float*)d_in[7];
    const float* bn_beta   = (const float*)d_in[8];
    const float* clf_W     = (const float*)d_in[9];
    const float* clf_b     = (const float*)d_in[10];
    float*       out       = (float*)d_out;

    __half2* Yi;
    __half *Ah, *Al, *Bh, *Bl, *Wph, *Wpm;
    float *ro, *stats9, *cvec9, *degw;
    int *cnt, *off, *cur, *csr, *bsum;
    cudaGetSymbolAddress((void**)&Yi,     g_Yi);
    cudaGetSymbolAddress((void**)&Ah,     g_Ah);
    cudaGetSymbolAddress((void**)&Al,     g_Al);
    cudaGetSymbolAddress((void**)&Bh,     g_Bh);
    cudaGetSymbolAddress((void**)&Bl,     g_Bl);
    cudaGetSymbolAddress((void**)&Wph,    g_Wph);
    cudaGetSymbolAddress((void**)&Wpm,    g_Wpm);
    cudaGetSymbolAddress((void**)&ro,     g_ro);
    cudaGetSymbolAddress((void**)&stats9, g_stats9);
    cudaGetSymbolAddress((void**)&cvec9,  g_cvec9);
    cudaGetSymbolAddress((void**)&degw,   g_degw);
    cudaGetSymbolAddress((void**)&cnt,    g_cnt);
    cudaGetSymbolAddress((void**)&off,    g_off);
    cudaGetSymbolAddress((void**)&cur,    g_cur);
    cudaGetSymbolAddress((void**)&csr,    g_csr);
    cudaGetSymbolAddress((void**)&bsum,   g_bsum);

    cudaFuncSetAttribute(gemm_tc_kernel,
                         cudaFuncAttributeMaxDynamicSharedMemorySize, GEMM_SMEM);

    encode_kernel<<<4096, 256>>>(node_vals, seq_W, seq_b, Yi);

    zero_cnt_kernel<<<N_NODES / 256, 256>>>(cnt);
    zero_misc_kernel<<<BATCH * ORDER / 4 * 1, 1024>>>(stats9, cvec9, ro);
    hist_kernel<<<N_EDGES / 512, 512>>>(edge_dst, cnt);
    scan1_kernel<<<256, 512>>>(cnt, bsum);
    scan2_kernel<<<1, 256>>>(bsum);
    scan3_kernel<<<256, 512>>>(cnt, bsum, off, cur, degw);
    fill_kernel<<<N_EDGES / 512, 512>>>(edge_src, edge_dst, cur, csr);

    const dim3 ggrid(2, N_NODES / 128);
    const dim3 pgrid(8, 8);
    const dim3 pblk(32, 32);

    for (int i = 0; i < ORDER; i++) {
        const int s0 = i * 3;
        for (int q = 0; q < 4; q++)
            gather_kernel<<<N_NODES / 8, 256>>>(Yi, Bh, Bl, off, cnt, csr, q);

        // sublayer s0: pending affine = sublayer s0-1 (identity for s0==0)
        {
            const float* sp = (s0 == 0) ? nullptr : stats9 + (size_t)(s0 - 1) * 512;
            const float* gp = (s0 == 0) ? nullptr : bn_gamma + (size_t)(s0 - 1) * RANK;
            const float* bp = (s0 == 0) ? nullptr : bn_beta  + (size_t)(s0 - 1) * RANK;
            prep_wfold_kernel<<<pgrid, pblk>>>(mlp_W + (size_t)s0 * 65536,
                                               sp, gp, bp, Wph, Wpm,
                                               cvec9 + (size_t)s0 * RANK);
        }
        gemm_tc_kernel<<<ggrid, 256, GEMM_SMEM>>>(
            Bh, Bl, Wph, Wpm, mlp_b + (size_t)s0 * RANK,
            cvec9 + (size_t)s0 * RANK, degw,
            Ah, Al, nullptr, stats9 + (size_t)s0 * 512, nullptr);

        prep_wfold_kernel<<<pgrid, pblk>>>(mlp_W + (size_t)(s0 + 1) * 65536,
                                           stats9 + (size_t)s0 * 512,
                                           bn_gamma + (size_t)s0 * RANK,
                                           bn_beta  + (size_t)s0 * RANK,
                                           Wph, Wpm, cvec9 + (size_t)(s0 + 1) * RANK);
        gemm_tc_kernel<<<ggrid, 256, GEMM_SMEM>>>(
            Ah, Al, Wph, Wpm, mlp_b + (size_t)(s0 + 1) * RANK,
            cvec9 + (size_t)(s0 + 1) * RANK, nullptr,
            Bh, Bl, nullptr, stats9 + (size_t)(s0 + 1) * 512, nullptr);

        prep_wfold_kernel<<<pgrid, pblk>>>(mlp_W + (size_t)(s0 + 2) * 65536,
                                           stats9 + (size_t)(s0 + 1) * 512,
                                           bn_gamma + (size_t)(s0 + 1) * RANK,
                                           bn_beta  + (size_t)(s0 + 1) * RANK,
                                           Wph, Wpm, cvec9 + (size_t)(s0 + 2) * RANK);
        gemm_tc_kernel<<<ggrid, 256, GEMM_SMEM>>>(
            Bh, Bl, Wph, Wpm, mlp_b + (size_t)(s0 + 2) * RANK,
            cvec9 + (size_t)(s0 + 2) * RANK, nullptr,
            nullptr, nullptr, Yi, stats9 + (size_t)(s0 + 2) * 512,
            ro + (size_t)i * RANK);

        scale_ro_kernel<<<BATCH, RANK>>>(ro + (size_t)i * RANK,
                                         stats9 + (size_t)(s0 + 2) * 512,
                                         bn_gamma + (size_t)(s0 + 2) * RANK,
                                         bn_beta  + (size_t)(s0 + 2) * RANK);
    }

    classifier_kernel<<<BATCH, N_CLASSES>>>(ro, clf_W, clf_b, out);
}

// round 13
// speedup vs baseline: 1.0933x; 1.0933x over previous
#include <cuda_runtime.h>
#include <cuda_fp16.h>
#include <cstdint>

#define N_NODES   131072
#define N_EDGES   2097152
#define RANK      256
#define L_FLOW    128
#define BATCH     1024
#define N_CLASSES 32
#define ORDER     3
#define BN_EPS    1e-5f

// ---------------------------------------------------------------------------
// Scratch
// ---------------------------------------------------------------------------
__device__ __half2 g_Yi[(size_t)N_NODES * RANK];   // interleaved (h,l)
__device__ __half  g_Ah[(size_t)N_NODES * RANK];
__device__ __half  g_Al[(size_t)N_NODES * RANK];
__device__ __half  g_Bh[(size_t)N_NODES * RANK];
__device__ __half  g_Bl[(size_t)N_NODES * RANK];
__device__ __half  g_Wph[RANK * RANK];
__device__ __half  g_Wpm[RANK * RANK];
__device__ float   g_ro[BATCH * RANK * ORDER];
__device__ float   g_stats9[9 * 2 * RANK];   // per-sublayer col sum/sumsq
__device__ float   g_cvec9[9 * RANK];        // per-sublayer bb^T W
__device__ float   g_degw[N_NODES];
__device__ int     g_cnt[N_NODES];
__device__ int     g_off[N_NODES];
__device__ int     g_cur[N_NODES];
__device__ int     g_csr[N_EDGES];
__device__ int     g_bsum[256];

__device__ __forceinline__ uint32_t smem_u32(const void* p) {
    uint32_t a;
    asm("{ .reg .u64 t; cvta.to.shared.u64 t, %1; cvt.u32.u64 %0, t; }"
        : "=r"(a) : "l"(p));
    return a;
}
__device__ __forceinline__ void ldsm_x4(uint32_t* r, uint32_t addr) {
    asm volatile("ldmatrix.sync.aligned.m8n8.x4.shared.b16 {%0,%1,%2,%3}, [%4];"
                 : "=r"(r[0]), "=r"(r[1]), "=r"(r[2]), "=r"(r[3]) : "r"(addr));
}
__device__ __forceinline__ void mma_f16(float* c, const uint32_t* a,
                                        uint32_t b0, uint32_t b1) {
    asm volatile(
        "mma.sync.aligned.m16n8k16.row.col.f32.f16.f16.f32 "
        "{%0,%1,%2,%3}, {%4,%5,%6,%7}, {%8,%9}, {%0,%1,%2,%3};"
        : "+f"(c[0]), "+f"(c[1]), "+f"(c[2]), "+f"(c[3])
        : "r"(a[0]), "r"(a[1]), "r"(a[2]), "r"(a[3]), "r"(b0), "r"(b1));
}
__device__ __forceinline__ void cp16(uint32_t s, const void* g) {
    asm volatile("cp.async.cg.shared.global [%0], [%1], 16;"
                 :: "r"(s), "l"(g) : "memory");
}
#define CP_COMMIT() asm volatile("cp.async.commit_group;" ::: "memory")
#define CP_WAIT0()  asm volatile("cp.async.wait_group 0;" ::: "memory")

__device__ __forceinline__ uint32_t pack_h2(float a, float b) {
    __half2 p = __halves2half2(__float2half_rn(a), __float2half_rn(b));
    return *(uint32_t*)&p;
}
__device__ __forceinline__ void st_cs_v2(void* p, uint32_t a, uint32_t b) {
    asm volatile("st.global.cs.v2.u32 [%0], {%1, %2};"
                 :: "l"(p), "r"(a), "r"(b) : "memory");
}

// ---------------------------------------------------------------------------
// 1) seq encoder -> interleaved Yi
// ---------------------------------------------------------------------------
__global__ void encode_kernel(const float* __restrict__ nv,
                              const float* __restrict__ sW,
                              const float* __restrict__ sb,
                              __half2* __restrict__ Yi) {
    const size_t total = (size_t)N_NODES * 32;
    for (size_t idx = (size_t)blockIdx.x * blockDim.x + threadIdx.x;
         idx < total; idx += (size_t)gridDim.x * blockDim.x) {
        size_t n = idx >> 5;
        int    q = (int)(idx & 31);
        float  x = __ldg(nv + n);
        float v[8];
        #pragma unroll
        for (int j = 0; j < 2; j++) {
            float4 w = __ldg((const float4*)sW + q * 2 + j);
            float4 b = __ldg((const float4*)sb + q * 2 + j);
            v[j * 4 + 0] = fmaf(x, w.x, b.x);
            v[j * 4 + 1] = fmaf(x, w.y, b.y);
            v[j * 4 + 2] = fmaf(x, w.z, b.z);
            v[j * 4 + 3] = fmaf(x, w.w, b.w);
        }
        uint4 o0, o1;
        uint32_t* p0 = (uint32_t*)&o0;
        uint32_t* p1 = (uint32_t*)&o1;
        #pragma unroll
        for (int j = 0; j < 4; j++) {
            float h0 = __half2float(__float2half_rn(v[j]));
            float h1 = __half2float(__float2half_rn(v[4 + j]));
            p0[j] = pack_h2(h0, v[j] - h0);
            p1[j] = pack_h2(h1, v[4 + j] - h1);
        }
        uint4* dst = (uint4*)(Yi + n * RANK + q * 8);
        dst[0] = o0;
        dst[1] = o1;
    }
}

// ---------------------------------------------------------------------------
// 2) CSR build + upfront zero
// ---------------------------------------------------------------------------
__global__ void zero_cnt_kernel(int* __restrict__ cnt) {
    cnt[blockIdx.x * blockDim.x + threadIdx.x] = 0;
}
__global__ void zero_misc_kernel(float* __restrict__ stats9,
                                 float* __restrict__ cvec9,
                                 float* __restrict__ ro) {
    const int i = blockIdx.x * blockDim.x + threadIdx.x;
    if (i < 9 * 2 * RANK) stats9[i] = 0.f;
    if (i < 9 * RANK)     cvec9[i]  = 0.f;
    if (i < BATCH * RANK * ORDER) ro[i] = 0.f;
}
__global__ void hist_kernel(const int* __restrict__ ed, int* __restrict__ cnt) {
    atomicAdd(&cnt[ed[blockIdx.x * blockDim.x + threadIdx.x]], 1);
}
__global__ void scan1_kernel(const int* __restrict__ cnt, int* __restrict__ bsum) {
    __shared__ int s[512];
    const int t = threadIdx.x;
    s[t] = cnt[blockIdx.x * 512 + t];
    __syncthreads();
    for (int o = 256; o > 0; o >>= 1) {
        if (t < o) s[t] += s[t + o];
        __syncthreads();
    }
    if (t == 0) bsum[blockIdx.x] = s[0];
}
__global__ void scan2_kernel(int* __restrict__ bsum) {
    __shared__ int s[256];
    const int t = threadIdx.x;
    int v = bsum[t];
    s[t] = v;
    __syncthreads();
    for (int o = 1; o < 256; o <<= 1) {
        int add = (t >= o) ? s[t - o] : 0;
        __syncthreads();
        s[t] += add;
        __syncthreads();
    }
    bsum[t] = s[t] - v;
}
__global__ void scan3_kernel(const int* __restrict__ cnt, const int* __restrict__ bsum,
                             int* __restrict__ off, int* __restrict__ cur,
                             float* __restrict__ degw) {
    __shared__ int s[512];
    const int t = threadIdx.x;
    const int base = blockIdx.x * 512;
    int v = cnt[base + t];
    s[t] = v;
    __syncthreads();
    for (int o = 1; o < 512; o <<= 1) {
        int add = (t >= o) ? s[t - o] : 0;
        __syncthreads();
        s[t] += add;
        __syncthreads();
    }
    int ex = s[t] - v + bsum[blockIdx.x];
    off[base + t]  = ex;
    cur[base + t]  = ex;
    degw[base + t] = 1.0f + (float)v;
}
__global__ void fill_kernel(const int* __restrict__ es, const int* __restrict__ ed,
                            int* __restrict__ cur, int* __restrict__ csr) {
    const int e = blockIdx.x * blockDim.x + threadIdx.x;
    int p = atomicAdd(&cur[ed[e]], 1);
    csr[p] = es[e];
}

// ---------------------------------------------------------------------------
// 3) gather (feature-HALF pass, 64MB working set — best measured config)
// ---------------------------------------------------------------------------
__global__ void gather_kernel(const __half2* __restrict__ Yi,
                              __half* __restrict__ Zh, __half* __restrict__ Zl,
                              const int* __restrict__ off,
                              const int* __restrict__ cnt,
                              const int* __restrict__ csr, int hf) {
    const int node = blockIdx.x * 8 + (threadIdx.x >> 5);
    const int lane = threadIdx.x & 31;
    const int foff = hf * 128;
    float acc[4];
    {
        uint4 v = __ldg((const uint4*)(Yi + (size_t)node * RANK + foff) + lane);
        const __half2* p = (const __half2*)&v;
        #pragma unroll
        for (int j = 0; j < 4; j++) {
            float2 f = __half22float2(p[j]);
            acc[j] = f.x + f.y;
        }
    }
    const int o = off[node];
    const int d = cnt[node];
    int j = 0;
    for (; j + 2 <= d; j += 2) {
        const size_t s0 = (size_t)__ldg(csr + o + j)     * RANK + foff;
        const size_t s1 = (size_t)__ldg(csr + o + j + 1) * RANK + foff;
        uint4 v0 = __ldg((const uint4*)(Yi + s0) + lane);
        uint4 v1 = __ldg((const uint4*)(Yi + s1) + lane);
        const __half2* p0 = (const __half2*)&v0;
        const __half2* p1 = (const __half2*)&v1;
        #pragma unroll
        for (int q = 0; q < 4; q++) {
            float2 f0 = __half22float2(p0[q]);
            float2 f1 = __half22float2(p1[q]);
            acc[q] += (f0.x + f0.y) + (f1.x + f1.y);
        }
    }
    if (j < d) {
        const size_t s = (size_t)__ldg(csr + o + j) * RANK + foff;
        uint4 v = __ldg((const uint4*)(Yi + s) + lane);
        const __half2* p = (const __half2*)&v;
        #pragma unroll
        for (int q = 0; q < 4; q++) {
            float2 f = __half22float2(p[q]);
            acc[q] += f.x + f.y;
        }
    }
    float h0 = __half2float(__float2half_rn(acc[0]));
    float h1 = __half2float(__float2half_rn(acc[1]));
    float h2 = __half2float(__float2half_rn(acc[2]));
    float h3 = __half2float(__float2half_rn(acc[3]));
    const size_t zo = (size_t)node * RANK + foff + lane * 4;
    st_cs_v2(Zh + zo, pack_h2(h0, h1), pack_h2(h2, h3));
    st_cs_v2(Zl + zo, pack_h2(acc[0] - h0, acc[1] - h1),
                      pack_h2(acc[2] - h2, acc[3] - h3));
}

// ---------------------------------------------------------------------------
// 4) weight fold with inline pending-BN affine
// ---------------------------------------------------------------------------
__global__ void prep_wfold_kernel(const float* __restrict__ W,
                                  const float* __restrict__ stats_prev,
                                  const float* __restrict__ gamma_prev,
                                  const float* __restrict__ beta_prev,
                                  __half* __restrict__ Wph,
                                  __half* __restrict__ Wpm,
                                  float* __restrict__ cvec) {
    __shared__ float t[32][33];
    __shared__ float cp[32][33];
    __shared__ float a_s[32], bb_s[32];
    const int tx = threadIdx.x, ty = threadIdx.y;
    if (ty == 0) {
        const int k = blockIdx.y * 32 + tx;
        float a = 1.f, bb = 0.f;
        if (stats_prev) {
            const float inv = 1.0f / (float)N_NODES;
            float m   = stats_prev[k] * inv;
            float var = fmaf(-m, m, stats_prev[RANK + k] * inv);
            a  = gamma_prev[k] * rsqrtf(var + BN_EPS);
            bb = fmaf(-m, a, beta_prev[k]);
        }
        a_s[tx]  = a;
        bb_s[tx] = bb;
    }
    const int k   = blockIdx.y * 32 + ty;
    const int out = blockIdx.x * 32 + tx;
    float w = W[(size_t)k * RANK + out];
    t[ty][tx] = w;
    __syncthreads();
    cp[ty][tx] = bb_s[ty] * w;
    __syncthreads();
    for (int o = 16; o > 0; o >>= 1) {
        if (ty < o) cp[ty][tx] += cp[ty + o][tx];
        __syncthreads();
    }
    if (ty == 0) atomicAdd(&cvec[out], cp[0][tx]);
    const int kp   = blockIdx.y * 32 + tx;
    const int outp = blockIdx.x * 32 + ty;
    float wv = a_s[tx] * t[tx][ty];
    __half h = __float2half_rn(wv);
    __half m = __float2half_rn(wv - __half2float(h));
    Wph[(size_t)outp * RANK + kp] = h;
    Wpm[(size_t)outp * RANK + kp] = m;
}

// ---------------------------------------------------------------------------
// 5) GEMM: 128x128 tile, 256 thr, 2-stage cp.async, one sync per k-chunk.
// ---------------------------------------------------------------------------
#define TS        80
#define TILE      (128 * TS)
#define STAGE     (4 * TILE)
#define GEMM_SMEM (2 * STAGE)

__global__ void __launch_bounds__(256, 2)
gemm_tc_kernel(const __half* __restrict__ Xh, const __half* __restrict__ Xl,
               const __half* __restrict__ Wph, const __half* __restrict__ Wpm,
               const float* __restrict__ bias, const float* __restrict__ cvec,
               const float* __restrict__ degw,
               __half* __restrict__ Yh, __half* __restrict__ Yl,
               __half2* __restrict__ Yi,
               float* __restrict__ stats, float* __restrict__ rosum) {
    extern __shared__ char smem[];
    const uint32_t sbase = smem_u32(smem);
    const int tid  = threadIdx.x;
    const int wid  = tid >> 5;
    const int lane = tid & 31;
    const int wm_  = wid & 3;
    const int wn   = wid >> 2;
    const int outbase = blockIdx.x * 128;
    const int x0      = blockIdx.y * 128;

    const int lr  = tid >> 1;
    const int lsb = (tid & 1) * 32;
    const int lsh = (tid & 1) * 16;
    const char* gsrc[4];
    gsrc[0] = (const char*)(Xh  + (size_t)(x0 + lr)      * RANK + lsh);
    gsrc[1] = (const char*)(Xl  + (size_t)(x0 + lr)      * RANK + lsh);
    gsrc[2] = (const char*)(Wph + (size_t)(outbase + lr) * RANK + lsh);
    gsrc[3] = (const char*)(Wpm + (size_t)(outbase + lr) * RANK + lsh);
    uint32_t sdst[4];
    #pragma unroll
    for (int t = 0; t < 4; t++) sdst[t] = sbase + t * TILE + lr * TS + lsb;

    float acc[2][8][4];
    #pragma unroll
    for (int mi = 0; mi < 2; mi++)
        #pragma unroll
        for (int nt = 0; nt < 8; nt++)
            #pragma unroll
            for (int e = 0; e < 4; e++) acc[mi][nt][e] = 0.f;

    const uint32_t aA = sbase + (uint32_t)(wm_ * 32 + (lane & 15)) * TS
                        + ((uint32_t)(lane >> 4) << 4);
    const uint32_t aB = sbase + 2 * TILE
                        + (uint32_t)(wn * 64 + ((lane >> 4) << 3) + (lane & 7)) * TS
                        + (((uint32_t)(lane >> 3) & 1) << 4);

    #pragma unroll
    for (int t = 0; t < 4; t++) {
        cp16(sdst[t],      gsrc[t]);
        cp16(sdst[t] + 16, gsrc[t] + 16);
    }
    CP_COMMIT();

    #pragma unroll 1
    for (int c = 0; c < 8; c++) {
        CP_WAIT0();
        __syncthreads();

        if (c < 7) {
            const int st = ((c + 1) & 1) * STAGE;
            const int go = (c + 1) * 64;
            #pragma unroll
            for (int t = 0; t < 4; t++) {
                cp16(sdst[t] + st,      gsrc[t] + go);
                cp16(sdst[t] + st + 16, gsrc[t] + go + 16);
            }
            CP_COMMIT();
        }

        const uint32_t st = (uint32_t)((c & 1) * STAGE);
        #pragma unroll
        for (int t = 0; t < 2; t++) {
            uint32_t ah[2][4], am[2][4];
            const uint32_t aAt = aA + st + t * 32;
            ldsm_x4(ah[0], aAt);
            ldsm_x4(ah[1], aAt + 16 * TS);
            ldsm_x4(am[0], aAt + TILE);
            ldsm_x4(am[1], aAt + TILE + 16 * TS);
            const uint32_t aBt = aB + st + t * 32;
            #pragma unroll
            for (int g = 0; g < 4; g++) {
                uint32_t bh[4], bm[4];
                ldsm_x4(bh, aBt + g * 16 * TS);
                ldsm_x4(bm, aBt + g * 16 * TS + TILE);
                #pragma unroll
                for (int mi = 0; mi < 2; mi++) {
                    #pragma unroll
                    for (int s = 0; s < 2; s++) {
                        float* cc = acc[mi][g * 2 + s];
                        mma_f16(cc, ah[mi], bh[2 * s], bh[2 * s + 1]);
                        mma_f16(cc, ah[mi], bm[2 * s], bm[2 * s + 1]);
                        mma_f16(cc, am[mi], bh[2 * s], bh[2 * s + 1]);
                    }
                }
            }
        }
    }

    // --- epilogue ---
    const int gid = lane >> 2, tig = lane & 3;
    float df[4] = {1.f, 1.f, 1.f, 1.f};
    if (degw) {
        const int rb = x0 + wm_ * 32 + gid;
        df[0] = degw[rb];
        df[1] = degw[rb + 8];
        df[2] = degw[rb + 16];
        df[3] = degw[rb + 24];
    }
    float ssum[8][2], ssq[8][2];
    #pragma unroll
    for (int nt = 0; nt < 8; nt++) {
        const int out = outbase + wn * 64 + nt * 8 + 2 * tig;
        const float b0 = __ldg(bias + out),  b1 = __ldg(bias + out + 1);
        const float c0 = __ldg(cvec + out),  c1 = __ldg(cvec + out + 1);
        float s0 = 0.f, s1 = 0.f, q0 = 0.f, q1 = 0.f;
        #pragma unroll
        for (int mi = 0; mi < 2; mi++) {
            const float* cc = acc[mi][nt];
            const int row = x0 + wm_ * 32 + mi * 16 + gid;
            float v00 = fmaxf(cc[0] + b0 + df[2 * mi] * c0, 0.f);
            float v01 = fmaxf(cc[1] + b1 + df[2 * mi] * c1, 0.f);
            float v10 = fmaxf(cc[2] + b0 + df[2 * mi + 1] * c0, 0.f);
            float v11 = fmaxf(cc[3] + b1 + df[2 * mi + 1] * c1, 0.f);
            float h00 = __half2float(__float2half_rn(v00));
            float h01 = __half2float(__float2half_rn(v01));
            float h10 = __half2float(__float2half_rn(v10));
            float h11 = __half2float(__float2half_rn(v11));
            if (Yi) {
                *(uint2*)(Yi + (size_t)row * RANK + out) =
                    make_uint2(pack_h2(h00, v00 - h00), pack_h2(h01, v01 - h01));
                *(uint2*)(Yi + (size_t)(row + 8) * RANK + out) =
                    make_uint2(pack_h2(h10, v10 - h10), pack_h2(h11, v11 - h11));
            } else {
                *(uint32_t*)(Yh + (size_t)row * RANK + out)       = pack_h2(h00, h01);
                *(uint32_t*)(Yl + (size_t)row * RANK + out)       = pack_h2(v00 - h00, v01 - h01);
                *(uint32_t*)(Yh + (size_t)(row + 8) * RANK + out) = pack_h2(h10, h11);
                *(uint32_t*)(Yl + (size_t)(row + 8) * RANK + out) = pack_h2(v10 - h10, v11 - h11);
            }
            s0 += v00 + v10;
            s1 += v01 + v11;
            q0 += v00 * v00 + v10 * v10;
            q1 += v01 * v01 + v11 * v11;
        }
        ssum[nt][0] = s0; ssum[nt][1] = s1;
        ssq[nt][0]  = q0; ssq[nt][1]  = q1;
    }
    #pragma unroll
    for (int nt = 0; nt < 8; nt++)
        #pragma unroll
        for (int e = 0; e < 2; e++) {
            float s = ssum[nt][e], q = ssq[nt][e];
            #pragma unroll
            for (int m = 4; m < 32; m <<= 1) {
                s += __shfl_xor_sync(0xFFFFFFFF, s, m);
                q += __shfl_xor_sync(0xFFFFFFFF, q, m);
            }
            ssum[nt][e] = s; ssq[nt][e] = q;
        }
    if (lane < 4) {
        float* rp = rosum ? rosum + (size_t)blockIdx.y * (RANK * ORDER) : nullptr;
        #pragma unroll
        for (int nt = 0; nt < 8; nt++) {
            const int out = outbase + wn * 64 + nt * 8 + 2 * tig;
            atomicAdd(&stats[out],            ssum[nt][0]);
            atomicAdd(&stats[out + 1],        ssum[nt][1]);
            atomicAdd(&stats[RANK + out],     ssq[nt][0]);
            atomicAdd(&stats[RANK + out + 1], ssq[nt][1]);
            if (rp) {
                atomicAdd(rp + out,     ssum[nt][0]);
                atomicAdd(rp + out + 1, ssum[nt][1]);
            }
        }
    }
}

// ---------------------------------------------------------------------------
// 6) readout scale: inline pending affine from final sublayer stats
// ---------------------------------------------------------------------------
__global__ void scale_ro_kernel(float* __restrict__ ro,
                                const float* __restrict__ stats,
                                const float* __restrict__ gamma,
                                const float* __restrict__ beta) {
    const int c = threadIdx.x;
    const float inv = 1.0f / (float)N_NODES;
    float m   = stats[c] * inv;
    float var = fmaf(-m, m, stats[RANK + c] * inv);
    float a   = gamma[c] * rsqrtf(var + BN_EPS);
    float bb  = fmaf(-m, a, beta[c]);
    float* p = ro + (size_t)blockIdx.x * (RANK * ORDER) + c;
    *p = fmaf(a, *p, 128.f * bb);
}

// ---------------------------------------------------------------------------
// 7) classifier
// ---------------------------------------------------------------------------
__global__ void classifier_kernel(const float* __restrict__ ro,
                                  const float* __restrict__ W,
                                  const float* __restrict__ b,
                                  float* __restrict__ out) {
    const int bi = blockIdx.x;
    const int c  = threadIdx.x;
    const float* r = ro + (size_t)bi * (RANK * ORDER);
    float acc = b[c];
    #pragma unroll 8
    for (int k = 0; k < RANK * ORDER; k++)
        acc = fmaf(r[k], W[(size_t)k * N_CLASSES + c], acc);
    out[(size_t)bi * N_CLASSES + c] = acc;
}

// ---------------------------------------------------------------------------
// Host driver
// ---------------------------------------------------------------------------
extern "C" void kernel_launch(void* const* d_in, const int* in_sizes, int n_in,
                              void* d_out, int out_size) {
    const float* node_vals = (const float*)d_in[0];
    const int*   edge_src  = (const int*)d_in[1];
    const int*   edge_dst  = (const int*)d_in[2];
    const float* seq_W     = (const float*)d_in[3];
    const float* seq_b     = (const float*)d_in[4];
    const float* mlp_W     = (const float*)d_in[5];
    const float* mlp_b     = (const float*)d_in[6];
    const float* bn_gamma  = (const float*)d_in[7];
    const float* bn_beta   = (const float*)d_in[8];
    const float* clf_W     = (const float*)d_in[9];
    const float* clf_b     = (const float*)d_in[10];
    float*       out       = (float*)d_out;

    __half2* Yi;
    __half *Ah, *Al, *Bh, *Bl, *Wph, *Wpm;
    float *ro, *stats9, *cvec9, *degw;
    int *cnt, *off, *cur, *csr, *bsum;
    cudaGetSymbolAddress((void**)&Yi,     g_Yi);
    cudaGetSymbolAddress((void**)&Ah,     g_Ah);
    cudaGetSymbolAddress((void**)&Al,     g_Al);
    cudaGetSymbolAddress((void**)&Bh,     g_Bh);
    cudaGetSymbolAddress((void**)&Bl,     g_Bl);
    cudaGetSymbolAddress((void**)&Wph,    g_Wph);
    cudaGetSymbolAddress((void**)&Wpm,    g_Wpm);
    cudaGetSymbolAddress((void**)&ro,     g_ro);
    cudaGetSymbolAddress((void**)&stats9, g_stats9);
    cudaGetSymbolAddress((void**)&cvec9,  g_cvec9);
    cudaGetSymbolAddress((void**)&degw,   g_degw);
    cudaGetSymbolAddress((void**)&cnt,    g_cnt);
    cudaGetSymbolAddress((void**)&off,    g_off);
    cudaGetSymbolAddress((void**)&cur,    g_cur);
    cudaGetSymbolAddress((void**)&csr,    g_csr);
    cudaGetSymbolAddress((void**)&bsum,   g_bsum);

    cudaFuncSetAttribute(gemm_tc_kernel,
                         cudaFuncAttributeMaxDynamicSharedMemorySize, GEMM_SMEM);

    encode_kernel<<<4096, 256>>>(node_vals, seq_W, seq_b, Yi);

    zero_cnt_kernel<<<N_NODES / 256, 256>>>(cnt);
    zero_misc_kernel<<<768, 1024>>>(stats9, cvec9, ro);
    hist_kernel<<<N_EDGES / 512, 512>>>(edge_dst, cnt);
    scan1_kernel<<<256, 512>>>(cnt, bsum);
    scan2_kernel<<<1, 256>>>(bsum);
    scan3_kernel<<<256, 512>>>(cnt, bsum, off, cur, degw);
    fill_kernel<<<N_EDGES / 512, 512>>>(edge_src, edge_dst, cur, csr);

    const dim3 ggrid(2, N_NODES / 128);
    const dim3 pgrid(8, 8);
    const dim3 pblk(32, 32);

    for (int i = 0; i < ORDER; i++) {
        const int s0 = i * 3;
        gather_kernel<<<N_NODES / 8, 256>>>(Yi, Bh, Bl, off, cnt, csr, 0);
        gather_kernel<<<N_NODES / 8, 256>>>(Yi, Bh, Bl, off, cnt, csr, 1);

        {
            const float* sp = (s0 == 0) ? nullptr : stats9 + (size_t)(s0 - 1) * 512;
            const float* gp = (s0 == 0) ? nullptr : bn_gamma + (size_t)(s0 - 1) * RANK;
            const float* bp = (s0 == 0) ? nullptr : bn_beta  + (size_t)(s0 - 1) * RANK;
            prep_wfold_kernel<<<pgrid, pblk>>>(mlp_W + (size_t)s0 * 65536,
                                               sp, gp, bp, Wph, Wpm,
                                               cvec9 + (size_t)s0 * RANK);
        }
        gemm_tc_kernel<<<ggrid, 256, GEMM_SMEM>>>(
            Bh, Bl, Wph, Wpm, mlp_b + (size_t)s0 * RANK,
            cvec9 + (size_t)s0 * RANK, degw,
            Ah, Al, nullptr, stats9 + (size_t)s0 * 512, nullptr);

        prep_wfold_kernel<<<pgrid, pblk>>>(mlp_W + (size_t)(s0 + 1) * 65536,
                                           stats9 + (size_t)s0 * 512,
                                           bn_gamma + (size_t)s0 * RANK,
                                           bn_beta  + (size_t)s0 * RANK,
                                           Wph, Wpm, cvec9 + (size_t)(s0 + 1) * RANK);
        gemm_tc_kernel<<<ggrid, 256, GEMM_SMEM>>>(
            Ah, Al, Wph, Wpm, mlp_b + (size_t)(s0 + 1) * RANK,
            cvec9 + (size_t)(s0 + 1) * RANK, nullptr,
            Bh, Bl, nullptr, stats9 + (size_t)(s0 + 1) * 512, nullptr);

        prep_wfold_kernel<<<pgrid, pblk>>>(mlp_W + (size_t)(s0 + 2) * 65536,
                                           stats9 + (size_t)(s0 + 1) * 512,
                                           bn_gamma + (size_t)(s0 + 1) * RANK,
                                           bn_beta  + (size_t)(s0 + 1) * RANK,
                                           Wph, Wpm, cvec9 + (size_t)(s0 + 2) * RANK);
        gemm_tc_kernel<<<ggrid, 256, GEMM_SMEM>>>(
            Bh, Bl, Wph, Wpm, mlp_b + (size_t)(s0 + 2) * RANK,
            cvec9 + (size_t)(s0 + 2) * RANK, nullptr,
            nullptr, nullptr, Yi, stats9 + (size_t)(s0 + 2) * 512,
            ro + (size_t)i * RANK);

        scale_ro_kernel<<<BATCH, RANK>>>(ro + (size_t)i * RANK,
                                         stats9 + (size_t)(s0 + 2) * 512,
                                         bn_gamma + (size_t)(s0 + 2) * RANK,
                                         bn_beta  + (size_t)(s0 + 2) * RANK);
    }

    classifier_kernel<<<BATCH, N_CLASSES>>>(ro, clf_W, clf_b, out);
}